// round 15
// baseline (speedup 1.0000x reference)
#include <cuda_runtime.h>
#include <cuda_bf16.h>
#include <cstdint>
#include <math.h>

// Problem constants
#define S_LEN 512
#define BATCH 64
#define DIM   512
#define HID   1024
#define G4H   4096
#define KSPLIT 8
#define OUTN  1000
#define NBLK  256
#define BH    (BATCH * HID)

#define W_ELEMS ((size_t)G4H * HID)
#define OFF_HH0 ((size_t)0)
#define OFF_IH1 (W_ELEMS)
#define OFF_HH1 (2 * W_ELEMS)
#define OFF_IH0 (3 * W_ELEMS)
#define WTOT    (3 * W_ELEMS + (size_t)G4H * DIM)
#define XTOT    ((size_t)BATCH * S_LEN * DIM)

// K=32 windows. Per buffer: Ahi 5120 | Alo 5120 | Bhi 10240 | Blo 10240 = 30720B
// 3-buffer ring -> 92160B  (2 CTAs/SM: 184320 <= 228KB)
#define SLDB 80             // smem row stride bytes (32 bf16 = 64B data + 16 pad)
#define A_LO_OFF 5120
#define B_HI_OFF 10240
#define B_LO_OFF 20480
#define BUFB     30720
#define NBUF     3
#define SMEM_BYTES (NBUF * BUFB)

typedef __nv_bfloat16 bf16;

// ---------------------------------------------------------------------------
// Device scratch
// ---------------------------------------------------------------------------
__device__ float g_XW0[(size_t)S_LEN * BATCH * G4H];           // 512MB x-part + biases
__device__ __align__(16) bf16 g_Whi[WTOT];
__device__ __align__(16) bf16 g_Wlo[WTOT];
__device__ __align__(16) bf16 g_xhi[XTOT];
__device__ __align__(16) bf16 g_xlo[XTOT];
__device__ float g_gp0[(size_t)KSPLIT * BATCH * G4H];
__device__ float g_gp1[(size_t)KSPLIT * BATCH * G4H];
__device__ float g_h[2][BH];
__device__ float g_c[2][BH];
__device__ __align__(16) bf16 g_hhi[2][BH];
__device__ __align__(16) bf16 g_hlo[2][BH];
__device__ unsigned g_bar_count;
__device__ unsigned g_bar_gen;

// ---------------------------------------------------------------------------
// PTX wrappers
// ---------------------------------------------------------------------------
__device__ __forceinline__ void cpa16(uint32_t dst, const void* src) {
    asm volatile("cp.async.cg.shared.global [%0], [%1], 16;" :: "r"(dst), "l"(src));
}
#define CP_COMMIT() asm volatile("cp.async.commit_group;")
#define CP_WAIT(n)  asm volatile("cp.async.wait_group %0;" :: "n"(n))

__device__ __forceinline__ void ldmx4(unsigned& r0, unsigned& r1, unsigned& r2, unsigned& r3,
                                      uint32_t addr) {
    asm volatile("ldmatrix.sync.aligned.m8n8.x4.shared.b16 {%0,%1,%2,%3}, [%4];"
        : "=r"(r0), "=r"(r1), "=r"(r2), "=r"(r3) : "r"(addr));
}
__device__ __forceinline__ void ldmx2(unsigned& r0, unsigned& r1, uint32_t addr) {
    asm volatile("ldmatrix.sync.aligned.m8n8.x2.shared.b16 {%0,%1}, [%2];"
        : "=r"(r0), "=r"(r1) : "r"(addr));
}
__device__ __forceinline__ void mma_bf16(float d[4], const unsigned a[4], const unsigned b[2]) {
    asm volatile("mma.sync.aligned.m16n8k16.row.col.f32.bf16.bf16.f32 "
        "{%0,%1,%2,%3}, {%4,%5,%6,%7}, {%8,%9}, {%0,%1,%2,%3};"
        : "+f"(d[0]), "+f"(d[1]), "+f"(d[2]), "+f"(d[3])
        : "r"(a[0]), "r"(a[1]), "r"(a[2]), "r"(a[3]), "r"(b[0]), "r"(b[1]));
}

// ---------------------------------------------------------------------------
// K=32 window staging. A[64x32] hi/lo: 256 chunks (1/thread).
// B[128x32] hi/lo: 512 chunks (2/thread).
// ---------------------------------------------------------------------------
__device__ __forceinline__ void stageA32(const bf16* __restrict__ Ahi,
                                         const bf16* __restrict__ Alo,
                                         size_t a_stride, size_t koff, uint32_t buf) {
    const int tid = threadIdx.x;
    const int row = tid >> 2, cc = tid & 3;
    const uint32_t d = buf + row * SLDB + cc * 16;
    const size_t g = (size_t)row * a_stride + koff + cc * 8;
    cpa16(d, Ahi + g);
    cpa16(d + A_LO_OFF, Alo + g);
}
__device__ __forceinline__ void stageB32(const bf16* __restrict__ Bhi,
                                         const bf16* __restrict__ Blo,
                                         size_t b_stride, size_t koff, uint32_t buf) {
    const int tid = threadIdx.x;
#pragma unroll
    for (int i = 0; i < 2; i++) {
        const int c = tid + 256 * i;
        const int row = c >> 2, cc = c & 3;
        const uint32_t d = buf + B_HI_OFF + row * SLDB + cc * 16;
        const size_t g = (size_t)row * b_stride + koff + cc * 8;
        cpa16(d, Bhi + g);
        cpa16(d + (B_LO_OFF - B_HI_OFF), Blo + g);
    }
}

// ---------------------------------------------------------------------------
// Compute one K=32 window: D[64x128] += A * B^T (3-term bf16)
// ---------------------------------------------------------------------------
__device__ __forceinline__ void mma_win32(uint32_t buf, uint32_t aoff, uint32_t boff,
                                          float d[4][2][4]) {
    const uint32_t Ah = buf, Al = buf + A_LO_OFF;
    const uint32_t Bh = buf + B_HI_OFF, Bl = buf + B_LO_OFF;
#pragma unroll
    for (int kq = 0; kq < 2; kq++) {
        unsigned bh[2][2], bl[2][2];
#pragma unroll
        for (int nf = 0; nf < 2; nf++) {
            ldmx2(bh[nf][0], bh[nf][1], Bh + nf * (8 * SLDB) + kq * 32 + boff);
            ldmx2(bl[nf][0], bl[nf][1], Bl + nf * (8 * SLDB) + kq * 32 + boff);
        }
#pragma unroll
        for (int mf = 0; mf < 4; mf++) {
            unsigned ah[4], al[4];
            ldmx4(ah[0], ah[1], ah[2], ah[3], Ah + mf * (16 * SLDB) + kq * 32 + aoff);
            ldmx4(al[0], al[1], al[2], al[3], Al + mf * (16 * SLDB) + kq * 32 + aoff);
#pragma unroll
            for (int nf = 0; nf < 2; nf++) {
                mma_bf16(d[mf][nf], ah, bh[nf]);   // hi*hi
                mma_bf16(d[mf][nf], ah, bl[nf]);   // hi*lo
                mma_bf16(d[mf][nf], al, bh[nf]);   // lo*hi
            }
        }
    }
}

__device__ __forceinline__ void zero_acc(float d[4][2][4]) {
#pragma unroll
    for (int mf = 0; mf < 4; mf++)
#pragma unroll
        for (int nf = 0; nf < 2; nf++)
#pragma unroll
            for (int i = 0; i < 4; i++) d[mf][nf][i] = 0.0f;
}

// Fragment offsets for ldmatrix source rows
__device__ __forceinline__ uint32_t calc_aoff() {
    const int lane = threadIdx.x & 31;
    return ((lane & 7) + ((lane >> 3) & 1) * 8) * SLDB + (lane >> 4) * 16;
}
__device__ __forceinline__ uint32_t calc_boff() {
    const int lane = threadIdx.x & 31, warp = threadIdx.x >> 5;
    return (warp * 16 + (lane & 7)) * SLDB + ((lane >> 3) & 1) * 16;
}

// ---------------------------------------------------------------------------
// Generic pipelined GEMM (3-ring, 1 sync/window):
//   D[64x128] += A[64 x 32*nwin] * B[128 x 32*nwin]^T
// ---------------------------------------------------------------------------
__device__ __forceinline__ void mma_gemm32(
    const bf16* __restrict__ Ahi, const bf16* __restrict__ Alo, size_t a_stride,
    const bf16* __restrict__ Bhi, const bf16* __restrict__ Blo, size_t b_stride,
    int nwin, float d[4][2][4], uint32_t smem_u, uint32_t aoff, uint32_t boff)
{
    stageA32(Ahi, Alo, a_stride, 0, smem_u);
    stageB32(Bhi, Blo, b_stride, 0, smem_u);
    CP_COMMIT();
    if (nwin > 1) {
        stageA32(Ahi, Alo, a_stride, 32, smem_u + BUFB);
        stageB32(Bhi, Blo, b_stride, 32, smem_u + BUFB);
    }
    CP_COMMIT();
#pragma unroll 1
    for (int w = 0; w < nwin; w++) {
        CP_WAIT(1);
        __syncthreads();
        const int w2 = w + 2;
        if (w2 < nwin) {
            const uint32_t buf = smem_u + (w2 % NBUF) * BUFB;
            stageA32(Ahi, Alo, a_stride, (size_t)w2 * 32, buf);
            stageB32(Bhi, Blo, b_stride, (size_t)w2 * 32, buf);
        }
        CP_COMMIT();
        mma_win32(smem_u + (w % NBUF) * BUFB, aoff, boff, d);
    }
}

// Store D frags to out[m][n_base + n], row stride rstride
__device__ __forceinline__ void store_frags(float* __restrict__ out, int rstride,
                                            int n_base, float d[4][2][4]) {
    const int lane = threadIdx.x & 31, warp = threadIdx.x >> 5;
    const int g = lane >> 2, tg = lane & 3;
#pragma unroll
    for (int mf = 0; mf < 4; mf++)
#pragma unroll
        for (int nf = 0; nf < 2; nf++) {
            const int m = mf * 16 + g;
            const int n = n_base + warp * 16 + nf * 8 + 2 * tg;
            *(float2*)&out[(size_t)m * rstride + n]       = make_float2(d[mf][nf][0], d[mf][nf][1]);
            *(float2*)&out[(size_t)(m + 8) * rstride + n] = make_float2(d[mf][nf][2], d[mf][nf][3]);
        }
}

// ---------------------------------------------------------------------------
// Prelude: decompose weights and x into bf16 hi/lo
// ---------------------------------------------------------------------------
__global__ void decomp_kernel(const float* __restrict__ whh0, const float* __restrict__ wih1,
                              const float* __restrict__ whh1, const float* __restrict__ wih0,
                              const float* __restrict__ x) {
    const size_t stride = (size_t)gridDim.x * blockDim.x;
    const size_t total = WTOT + XTOT;
    for (size_t i = (size_t)blockIdx.x * blockDim.x + threadIdx.x; i < total; i += stride) {
        float v;
        bf16 *dh, *dl;
        if (i < WTOT) {
            size_t j = i;
            const float* src;
            if (j < W_ELEMS) src = whh0;
            else if (j < 2 * W_ELEMS) { src = wih1; j -= W_ELEMS; }
            else if (j < 3 * W_ELEMS) { src = whh1; j -= 2 * W_ELEMS; }
            else { src = wih0; j -= 3 * W_ELEMS; }
            v = src[j];
            dh = &g_Whi[i]; dl = &g_Wlo[i];
        } else {
            const size_t j = i - WTOT;
            v = x[j];
            dh = &g_xhi[j]; dl = &g_xlo[j];
        }
        const bf16 hi = __float2bfloat16_rn(v);
        *dh = hi;
        *dl = __float2bfloat16_rn(v - __bfloat162float(hi));
    }
}

__global__ void init_state_kernel(const float* __restrict__ h0,
                                  const float* __restrict__ c0) {
    const int i = blockIdx.x * blockDim.x + threadIdx.x;
    if (i < 2 * BH) {
        const float h = h0[i];
        ((float*)g_h)[i] = h;
        ((float*)g_c)[i] = c0[i];
        const bf16 hi = __float2bfloat16_rn(h);
        ((bf16*)g_hhi)[i] = hi;
        ((bf16*)g_hlo)[i] = __float2bfloat16_rn(h - __bfloat162float(hi));
    }
}

// ---------------------------------------------------------------------------
// Prelude GEMM: XW0[t] = x_t @ W_ih0^T + b_ih0 + b_hh0  (16 K=32 windows)
// ---------------------------------------------------------------------------
__global__ __launch_bounds__(256, 2) void xw0_mma_kernel(
    const float* __restrict__ b_ih0, const float* __restrict__ b_hh0)
{
    extern __shared__ char sm[];
    const uint32_t smem_u = (uint32_t)__cvta_generic_to_shared(sm);
    const int nt = blockIdx.x, t = blockIdx.y;
    const int n0 = nt * 128;
    const uint32_t aoff = calc_aoff(), boff = calc_boff();

    float d[4][2][4];
    zero_acc(d);
    mma_gemm32(g_xhi + (size_t)t * DIM, g_xlo + (size_t)t * DIM, (size_t)S_LEN * DIM,
               g_Whi + OFF_IH0 + (size_t)n0 * DIM, g_Wlo + OFF_IH0 + (size_t)n0 * DIM, DIM,
               DIM / 32, d, smem_u, aoff, boff);

    const int lane = threadIdx.x & 31, warp = threadIdx.x >> 5;
    const int g = lane >> 2, tg = lane & 3;
    float* out = g_XW0 + (size_t)t * BATCH * G4H;
#pragma unroll
    for (int nf = 0; nf < 2; nf++) {
        const int n = n0 + warp * 16 + nf * 8 + 2 * tg;
        const float bi0 = b_ih0[n] + b_hh0[n];
        const float bi1 = b_ih0[n + 1] + b_hh0[n + 1];
#pragma unroll
        for (int mf = 0; mf < 4; mf++) {
            const int m = mf * 16 + g;
            *(float2*)&out[(size_t)m * G4H + n] =
                make_float2(d[mf][nf][0] + bi0, d[mf][nf][1] + bi1);
            *(float2*)&out[(size_t)(m + 8) * G4H + n] =
                make_float2(d[mf][nf][2] + bi0, d[mf][nf][3] + bi1);
        }
    }
}

// ---------------------------------------------------------------------------
// Software grid barrier
// ---------------------------------------------------------------------------
__device__ __forceinline__ void grid_bar() {
    __syncthreads();
    if (threadIdx.x == 0) {
        __threadfence();
        const unsigned gen = *(volatile unsigned*)&g_bar_gen;
        if (atomicAdd(&g_bar_count, 1u) == NBLK - 1) {
            g_bar_count = 0;
            __threadfence();
            *(volatile unsigned*)&g_bar_gen = gen + 1;
        } else {
            while (*(volatile unsigned*)&g_bar_gen == gen) {}
        }
        __threadfence();
    }
    __syncthreads();
}

// ---------------------------------------------------------------------------
// LSTM cell math (refreshes bf16 hi/lo of h)
// ---------------------------------------------------------------------------
__device__ __forceinline__ void cell_update(int layer, int cidx, float v0, float v1,
                                            float v2, float v3) {
    const float ig = 1.0f / (1.0f + expf(-v0));
    const float fg = 1.0f / (1.0f + expf(-v1));
    const float gg = tanhf(v2);
    const float og = 1.0f / (1.0f + expf(-v3));
    const float c_new = fg * g_c[layer][cidx] + ig * gg;
    g_c[layer][cidx] = c_new;
    const float h = og * tanhf(c_new);
    g_h[layer][cidx] = h;
    const bf16 hi = __float2bfloat16_rn(h);
    g_hhi[layer][cidx] = hi;
    g_hlo[layer][cidx] = __float2bfloat16_rn(h - __bfloat162float(hi));
}

// ---------------------------------------------------------------------------
// Persistent recurrence. Per tick:
//   cell phase : cell0(t) + cell1(t-1); then PREFETCH B of windows 0,1
//   grid_bar
//   gemm phase : unified 12-window pipeline: L1(t) (8 wins) -> g_gp1,
//                then L0(t+1) (4 wins) -> g_gp0, hot pipeline throughout
//   grid_bar
// ---------------------------------------------------------------------------
__global__ __launch_bounds__(256, 2) void lstm_persistent_kernel(
    const float* __restrict__ b_ih1, const float* __restrict__ b_hh1)
{
    extern __shared__ char sm[];
    const uint32_t smem_u = (uint32_t)__cvta_generic_to_shared(sm);
    const int bid = blockIdx.x;
    const int nt = bid & 31, ks = bid >> 5;
    const int n0 = nt * 128;
    const int cidx = bid * 256 + threadIdx.x;
    const int cm = cidx >> 10, cj = cidx & (HID - 1);
    const uint32_t aoff = calc_aoff(), boff = calc_boff();

    // L1 operand mapping: ks<4 -> h0 x W_ih1, ks>=4 -> h1 x W_hh1
    const int ks1 = (ks < 4) ? ks * 256 : (ks - 4) * 256;
    const int l1layer = (ks < 4) ? 0 : 1;
    const bf16* A1hi = g_hhi[l1layer] + ks1;
    const bf16* A1lo = g_hlo[l1layer] + ks1;
    const bf16* B1hi = g_Whi + ((ks < 4) ? OFF_IH1 : OFF_HH1) + (size_t)n0 * HID + ks1;
    const bf16* B1lo = g_Wlo + ((ks < 4) ? OFF_IH1 : OFF_HH1) + (size_t)n0 * HID + ks1;
    // L0 operands
    const bf16* A0hi = g_hhi[0] + ks * 128;
    const bf16* A0lo = g_hlo[0] + ks * 128;
    const bf16* B0hi = g_Whi + OFF_HH0 + (size_t)n0 * HID + ks * 128;
    const bf16* B0lo = g_Wlo + OFF_HH0 + (size_t)n0 * HID + ks * 128;

    float* gp1_out = g_gp1 + (size_t)ks * BATCH * G4H;
    float* gp0_out = g_gp0 + (size_t)ks * BATCH * G4H;

    // prologue: L0 GEMM for t=0
    {
        float d[4][2][4];
        zero_acc(d);
        mma_gemm32(A0hi, A0lo, HID, B0hi, B0lo, HID, 4, d, smem_u, aoff, boff);
        store_frags(gp0_out, G4H, n0, d);
    }
    grid_bar();

#pragma unroll 1
    for (int t = 0; t < S_LEN; ++t) {
        // ---- cell phase ----
        {
            float v[4];
#pragma unroll
            for (int gt = 0; gt < 4; gt++) {
                const int n = gt * HID + cj;
                float s = g_XW0[((size_t)t * BATCH + cm) * G4H + n];
#pragma unroll
                for (int ss = 0; ss < KSPLIT; ss++)
                    s += g_gp0[((size_t)ss * BATCH + cm) * G4H + n];
                v[gt] = s;
            }
            cell_update(0, cidx, v[0], v[1], v[2], v[3]);

            if (t > 0) {
#pragma unroll
                for (int gt = 0; gt < 4; gt++) {
                    const int n = gt * HID + cj;
                    float s = b_ih1[n] + b_hh1[n];
#pragma unroll
                    for (int ss = 0; ss < KSPLIT; ss++)
                        s += g_gp1[((size_t)ss * BATCH + cm) * G4H + n];
                    v[gt] = s;
                }
                cell_update(1, cidx, v[0], v[1], v[2], v[3]);
            }
        }
        // prefetch B (weights, static) of windows 0,1 into the barrier shadow
        stageB32(B1hi, B1lo, HID, 0, smem_u);
        CP_COMMIT();
        stageB32(B1hi, B1lo, HID, 32, smem_u + BUFB);
        CP_COMMIT();
        grid_bar();
        // A (h-state) only valid after the barrier
        stageA32(A1hi, A1lo, HID, 0, smem_u);
        CP_COMMIT();
        stageA32(A1hi, A1lo, HID, 32, smem_u + BUFB);
        CP_COMMIT();

        // ---- unified gemm phase: 8 L1 windows, then 4 L0 windows ----
        {
            const int NW = (t + 1 < S_LEN) ? 12 : 8;
            float d[4][2][4];
            zero_acc(d);
#pragma unroll 1
            for (int w = 0; w < NW; w++) {
                CP_WAIT(1);
                __syncthreads();
                const int w2 = w + 2;
                if (w2 < NW) {
                    const uint32_t buf = smem_u + (w2 % NBUF) * BUFB;
                    if (w2 < 8) {
                        stageA32(A1hi, A1lo, HID, (size_t)w2 * 32, buf);
                        stageB32(B1hi, B1lo, HID, (size_t)w2 * 32, buf);
                    } else {
                        stageA32(A0hi, A0lo, HID, (size_t)(w2 - 8) * 32, buf);
                        stageB32(B0hi, B0lo, HID, (size_t)(w2 - 8) * 32, buf);
                    }
                }
                CP_COMMIT();
                mma_win32(smem_u + (w % NBUF) * BUFB, aoff, boff, d);
                if (w == 7) {
                    store_frags(gp1_out, G4H, n0, d);
                    zero_acc(d);
                }
            }
            if (NW == 12) store_frags(gp0_out, G4H, n0, d);
        }
        grid_bar();
    }

    // final cell1(S_LEN-1)
    {
        float v[4];
#pragma unroll
        for (int gt = 0; gt < 4; gt++) {
            const int n = gt * HID + cj;
            float s = b_ih1[n] + b_hh1[n];
#pragma unroll
            for (int ss = 0; ss < KSPLIT; ss++)
                s += g_gp1[((size_t)ss * BATCH + cm) * G4H + n];
            v[gt] = s;
        }
        cell_update(1, cidx, v[0], v[1], v[2], v[3]);
    }
}

// ---------------------------------------------------------------------------
// Final FC: out = h1 @ W_fc^T + b_fc
// ---------------------------------------------------------------------------
__global__ void fc_kernel(const float* __restrict__ Wfc,
                          const float* __restrict__ bfc,
                          float* __restrict__ out)
{
    const int gwarp = (blockIdx.x * blockDim.x + threadIdx.x) >> 5;
    const int lane  = threadIdx.x & 31;
    if (gwarp >= BATCH * OUTN) return;
    const int m = gwarp / OUTN;
    const int o = gwarp % OUTN;
    const float* hp = g_h[1] + (size_t)m * HID;
    const float* wp = Wfc + (size_t)o * HID;
    float s = 0.0f;
#pragma unroll 8
    for (int k = lane; k < HID; k += 32) s += hp[k] * wp[k];
#pragma unroll
    for (int off = 16; off; off >>= 1) s += __shfl_xor_sync(0xffffffffu, s, off);
    if (lane == 0) out[m * OUTN + o] = s + bfc[o];
}

// ---------------------------------------------------------------------------
// Launch: 5 graph nodes
// ---------------------------------------------------------------------------
extern "C" void kernel_launch(void* const* d_in, const int* in_sizes, int n_in,
                              void* d_out, int out_size) {
    const float* x      = (const float*)d_in[0];
    const float* h0     = (const float*)d_in[1];
    const float* c0     = (const float*)d_in[2];
    const float* W_ih0  = (const float*)d_in[3];
    const float* W_hh0  = (const float*)d_in[4];
    const float* b_ih0  = (const float*)d_in[5];
    const float* b_hh0  = (const float*)d_in[6];
    const float* W_ih1  = (const float*)d_in[7];
    const float* W_hh1  = (const float*)d_in[8];
    const float* b_ih1  = (const float*)d_in[9];
    const float* b_hh1  = (const float*)d_in[10];
    const float* W_fc   = (const float*)d_in[11];
    const float* b_fc   = (const float*)d_in[12];
    float* out = (float*)d_out;

    cudaFuncSetAttribute(xw0_mma_kernel,
                         cudaFuncAttributeMaxDynamicSharedMemorySize, SMEM_BYTES);
    cudaFuncSetAttribute(lstm_persistent_kernel,
                         cudaFuncAttributeMaxDynamicSharedMemorySize, SMEM_BYTES);

    decomp_kernel<<<4096, 256>>>(W_hh0, W_ih1, W_hh1, W_ih0, x);
    init_state_kernel<<<512, 256>>>(h0, c0);
    xw0_mma_kernel<<<dim3(32, S_LEN), 256, SMEM_BYTES>>>(b_ih0, b_hh0);
    lstm_persistent_kernel<<<NBLK, 256, SMEM_BYTES>>>(b_ih1, b_hh1);
    fc_kernel<<<(BATCH * OUTN + 7) / 8, 256>>>(W_fc, b_fc, out);
}

// round 16
// speedup vs baseline: 1.2668x; 1.2668x over previous
#include <cuda_runtime.h>
#include <cuda.h>
#include <cuda_bf16.h>
#include <cstdint>
#include <math.h>

// Problem constants
#define S_LEN 512
#define BATCH 64
#define DIM   512
#define HID   1024
#define G4H   4096
#define KSPLIT 8
#define OUTN  1000
#define NBLK  256
#define BH    (BATCH * HID)

#define W_ELEMS ((size_t)G4H * HID)
#define OFF_HH0 ((size_t)0)
#define OFF_IH1 (W_ELEMS)
#define OFF_HH1 (2 * W_ELEMS)
#define OFF_IH0 (3 * W_ELEMS)
#define WTOT    (3 * W_ELEMS + (size_t)G4H * DIM)
#define XTOT    ((size_t)BATCH * S_LEN * DIM)

// K=64 windows, SW128-swizzled 128B rows (TMA-filled).
// Buffer: Ahi 8K | Alo 8K | Bhi 16K | Blo 16K = 48KB. 2 buffers + mbars.
#define A_LO  8192
#define B_HI  16384
#define B_LO  32768
#define BUFB  49152
#define TXB   49152u
#define SMEM_BYTES (2 * BUFB + 64)

typedef __nv_bfloat16 bf16;

// ---------------------------------------------------------------------------
// Device scratch
// ---------------------------------------------------------------------------
__device__ float g_XW0[(size_t)S_LEN * BATCH * G4H];
__device__ __align__(256) bf16 g_Whi[WTOT];
__device__ __align__(256) bf16 g_Wlo[WTOT];
__device__ __align__(256) bf16 g_xhi[XTOT];
__device__ __align__(256) bf16 g_xlo[XTOT];
__device__ float g_gp0[(size_t)KSPLIT * BATCH * G4H];
__device__ float g_gp1[(size_t)KSPLIT * BATCH * G4H];
__device__ float g_h[2][BH];
__device__ float g_c[2][BH];
__device__ __align__(256) bf16 g_hhi[2][BH];
__device__ __align__(256) bf16 g_hlo[2][BH];
__device__ unsigned g_bar_count;
__device__ unsigned g_bar_gen;

// ---------------------------------------------------------------------------
// PTX wrappers
// ---------------------------------------------------------------------------
__device__ __forceinline__ void tma2d(uint32_t dst, const CUtensorMap* m, int x, int y,
                                      uint32_t bar) {
    asm volatile("cp.async.bulk.tensor.2d.shared::cta.global.tile.mbarrier::complete_tx::bytes "
                 "[%0], [%1, {%2, %3}], [%4];"
                 :: "r"(dst), "l"(m), "r"(x), "r"(y), "r"(bar) : "memory");
}
__device__ __forceinline__ void tma3d(uint32_t dst, const CUtensorMap* m, int x, int y, int z,
                                      uint32_t bar) {
    asm volatile("cp.async.bulk.tensor.3d.shared::cta.global.tile.mbarrier::complete_tx::bytes "
                 "[%0], [%1, {%2, %3, %4}], [%5];"
                 :: "r"(dst), "l"(m), "r"(x), "r"(y), "r"(z), "r"(bar) : "memory");
}
__device__ __forceinline__ void mbar_init(uint32_t mb, unsigned cnt) {
    asm volatile("mbarrier.init.shared.b64 [%0], %1;" :: "r"(mb), "r"(cnt) : "memory");
}
__device__ __forceinline__ void mbar_expect(uint32_t mb, unsigned tx) {
    asm volatile("mbarrier.arrive.expect_tx.shared.b64 _, [%0], %1;" :: "r"(mb), "r"(tx) : "memory");
}
__device__ __forceinline__ void mbar_wait(uint32_t mb, unsigned ph) {
    asm volatile("{\n\t.reg .pred P;\n\t"
                 "W_%=: mbarrier.try_wait.parity.acquire.cta.shared::cta.b64 P, [%0], %1, 0x989680;\n\t"
                 "@P bra D_%=;\n\t"
                 "bra W_%=;\n\t"
                 "D_%=:\n\t}" :: "r"(mb), "r"(ph) : "memory");
}
__device__ __forceinline__ void ldmx4(unsigned& r0, unsigned& r1, unsigned& r2, unsigned& r3,
                                      uint32_t addr) {
    asm volatile("ldmatrix.sync.aligned.m8n8.x4.shared.b16 {%0,%1,%2,%3}, [%4];"
        : "=r"(r0), "=r"(r1), "=r"(r2), "=r"(r3) : "r"(addr));
}
__device__ __forceinline__ void ldmx2(unsigned& r0, unsigned& r1, uint32_t addr) {
    asm volatile("ldmatrix.sync.aligned.m8n8.x2.shared.b16 {%0,%1}, [%2];"
        : "=r"(r0), "=r"(r1) : "r"(addr));
}
__device__ __forceinline__ void mma_bf16(float d[4], const unsigned a[4], const unsigned b[2]) {
    asm volatile("mma.sync.aligned.m16n8k16.row.col.f32.bf16.bf16.f32 "
        "{%0,%1,%2,%3}, {%4,%5,%6,%7}, {%8,%9}, {%0,%1,%2,%3};"
        : "+f"(d[0]), "+f"(d[1]), "+f"(d[2]), "+f"(d[3])
        : "r"(a[0]), "r"(a[1]), "r"(a[2]), "r"(a[3]), "r"(b[0]), "r"(b[1]));
}

// ---------------------------------------------------------------------------
// One K=64 window of D[64x128] += A * B^T, 3-term bf16, SW128-swizzled smem.
// Swizzle identity: addr = row*128 + ((seg ^ (row&7))<<4), seg = 16B column.
// ---------------------------------------------------------------------------
__device__ __forceinline__ void mma_win64(uint32_t buf, float d[4][2][4]) {
    const int lane = threadIdx.x & 31, warp = threadIdx.x >> 5;
    const int arow = (lane & 7) + ((lane >> 3) & 1) * 8;     // A row 0..15 in frag pair
    const int axr  = lane & 7;                               // row&7 (A and B rows alike)
    const int abs_ = lane >> 4;                              // A 16B half select
    const int bbs  = (lane >> 3) & 1;                        // B 16B half select
    const uint32_t aRB = buf + arow * 128;
    const uint32_t bRB = buf + B_HI + (warp * 16 + (lane & 7)) * 128;
#pragma unroll
    for (int kq = 0; kq < 4; kq++) {
        const uint32_t sa = (uint32_t)(((kq * 2 + abs_) ^ axr) << 4);
        const uint32_t sb = (uint32_t)(((kq * 2 + bbs) ^ axr) << 4);
        unsigned bh[2][2], bl[2][2];
#pragma unroll
        for (int nf = 0; nf < 2; nf++) {
            const uint32_t ba = bRB + nf * (8 * 128) + sb;
            ldmx2(bh[nf][0], bh[nf][1], ba);
            ldmx2(bl[nf][0], bl[nf][1], ba + (B_LO - B_HI));
        }
#pragma unroll
        for (int mf = 0; mf < 4; mf++) {
            const uint32_t aa = aRB + mf * (16 * 128) + sa;
            unsigned ah[4], al[4];
            ldmx4(ah[0], ah[1], ah[2], ah[3], aa);
            ldmx4(al[0], al[1], al[2], al[3], aa + A_LO);
#pragma unroll
            for (int nf = 0; nf < 2; nf++) {
                mma_bf16(d[mf][nf], ah, bh[nf]);   // hi*hi
                mma_bf16(d[mf][nf], ah, bl[nf]);   // hi*lo
                mma_bf16(d[mf][nf], al, bh[nf]);   // lo*hi
            }
        }
    }
}

__device__ __forceinline__ void zero_acc(float d[4][2][4]) {
#pragma unroll
    for (int mf = 0; mf < 4; mf++)
#pragma unroll
        for (int nf = 0; nf < 2; nf++)
#pragma unroll
            for (int i = 0; i < 4; i++) d[mf][nf][i] = 0.0f;
}

__device__ __forceinline__ void issue_win2d(uint32_t buf, uint32_t bar,
    const CUtensorMap* Ah, const CUtensorMap* Al, int ax,
    const CUtensorMap* Bh, const CUtensorMap* Bl, int bx, int by)
{
    mbar_expect(bar, TXB);
    tma2d(buf,        Ah, ax, 0, bar);
    tma2d(buf + A_LO, Al, ax, 0, bar);
    tma2d(buf + B_HI, Bh, bx, by, bar);
    tma2d(buf + B_LO, Bl, bx, by, bar);
}

// Store D frags to out[m][n_base + n], row stride rstride
__device__ __forceinline__ void store_frags(float* __restrict__ out, int rstride,
                                            int n_base, float d[4][2][4]) {
    const int lane = threadIdx.x & 31, warp = threadIdx.x >> 5;
    const int g = lane >> 2, tg = lane & 3;
#pragma unroll
    for (int mf = 0; mf < 4; mf++)
#pragma unroll
        for (int nf = 0; nf < 2; nf++) {
            const int m = mf * 16 + g;
            const int n = n_base + warp * 16 + nf * 8 + 2 * tg;
            *(float2*)&out[(size_t)m * rstride + n]       = make_float2(d[mf][nf][0], d[mf][nf][1]);
            *(float2*)&out[(size_t)(m + 8) * rstride + n] = make_float2(d[mf][nf][2], d[mf][nf][3]);
        }
}

// ---------------------------------------------------------------------------
// Prelude: decompose weights and x into bf16 hi/lo
// ---------------------------------------------------------------------------
__global__ void decomp_kernel(const float* __restrict__ whh0, const float* __restrict__ wih1,
                              const float* __restrict__ whh1, const float* __restrict__ wih0,
                              const float* __restrict__ x) {
    const size_t stride = (size_t)gridDim.x * blockDim.x;
    const size_t total = WTOT + XTOT;
    for (size_t i = (size_t)blockIdx.x * blockDim.x + threadIdx.x; i < total; i += stride) {
        float v;
        bf16 *dh, *dl;
        if (i < WTOT) {
            size_t j = i;
            const float* src;
            if (j < W_ELEMS) src = whh0;
            else if (j < 2 * W_ELEMS) { src = wih1; j -= W_ELEMS; }
            else if (j < 3 * W_ELEMS) { src = whh1; j -= 2 * W_ELEMS; }
            else { src = wih0; j -= 3 * W_ELEMS; }
            v = src[j];
            dh = &g_Whi[i]; dl = &g_Wlo[i];
        } else {
            const size_t j = i - WTOT;
            v = x[j];
            dh = &g_xhi[j]; dl = &g_xlo[j];
        }
        const bf16 hi = __float2bfloat16_rn(v);
        *dh = hi;
        *dl = __float2bfloat16_rn(v - __bfloat162float(hi));
    }
}

__global__ void init_state_kernel(const float* __restrict__ h0,
                                  const float* __restrict__ c0) {
    const int i = blockIdx.x * blockDim.x + threadIdx.x;
    if (i < 2 * BH) {
        const float h = h0[i];
        ((float*)g_h)[i] = h;
        ((float*)g_c)[i] = c0[i];
        const bf16 hi = __float2bfloat16_rn(h);
        ((bf16*)g_hhi)[i] = hi;
        ((bf16*)g_hlo)[i] = __float2bfloat16_rn(h - __bfloat162float(hi));
    }
}

// ---------------------------------------------------------------------------
// Prelude GEMM: XW0[t] = x_t @ W_ih0^T + b_ih0 + b_hh0.  8 K=64 TMA windows.
// x map is 3D (d, t, m); W map is 2D.
// ---------------------------------------------------------------------------
__global__ __launch_bounds__(256, 2) void xw0_mma_kernel(
    const __grid_constant__ CUtensorMap mXh, const __grid_constant__ CUtensorMap mXl,
    const __grid_constant__ CUtensorMap mWh, const __grid_constant__ CUtensorMap mWl,
    const float* __restrict__ b_ih0, const float* __restrict__ b_hh0)
{
    extern __shared__ __align__(1024) char sm[];
    const uint32_t smem_u = (uint32_t)__cvta_generic_to_shared(sm);
    const uint32_t mbar_u = smem_u + 2 * BUFB;
    const int nt = blockIdx.x, t = blockIdx.y;
    const int n0 = nt * 128;
    const int tid = threadIdx.x;

    if (tid == 0) { mbar_init(mbar_u, 1); mbar_init(mbar_u + 8, 1); }
    __syncthreads();

    const int NW = DIM / 64;  // 8
    if (tid == 0) {
#pragma unroll
        for (int w = 0; w < 2; w++) {
            const uint32_t buf = smem_u + (w & 1) * BUFB;
            const uint32_t bar = mbar_u + (w & 1) * 8;
            mbar_expect(bar, TXB);
            tma3d(buf,        &mXh, w * 64, t, 0, bar);
            tma3d(buf + A_LO, &mXl, w * 64, t, 0, bar);
            tma2d(buf + B_HI, &mWh, w * 64, n0, bar);
            tma2d(buf + B_LO, &mWl, w * 64, n0, bar);
        }
    }

    float d[4][2][4];
    zero_acc(d);
#pragma unroll 1
    for (int w = 0; w < NW; w++) {
        mbar_wait(mbar_u + (w & 1) * 8, (unsigned)((w >> 1) & 1));
        mma_win64(smem_u + (w & 1) * BUFB, d);
        __syncthreads();
        const int w2 = w + 2;
        if (tid == 0 && w2 < NW) {
            const uint32_t buf = smem_u + (w2 & 1) * BUFB;
            const uint32_t bar = mbar_u + (w2 & 1) * 8;
            mbar_expect(bar, TXB);
            tma3d(buf,        &mXh, w2 * 64, t, 0, bar);
            tma3d(buf + A_LO, &mXl, w2 * 64, t, 0, bar);
            tma2d(buf + B_HI, &mWh, w2 * 64, n0, bar);
            tma2d(buf + B_LO, &mWl, w2 * 64, n0, bar);
        }
    }

    const int lane = threadIdx.x & 31, warp = threadIdx.x >> 5;
    const int g = lane >> 2, tg = lane & 3;
    float* out = g_XW0 + (size_t)t * BATCH * G4H;
#pragma unroll
    for (int nf = 0; nf < 2; nf++) {
        const int n = n0 + warp * 16 + nf * 8 + 2 * tg;
        const float bi0 = b_ih0[n] + b_hh0[n];
        const float bi1 = b_ih0[n + 1] + b_hh0[n + 1];
#pragma unroll
        for (int mf = 0; mf < 4; mf++) {
            const int m = mf * 16 + g;
            *(float2*)&out[(size_t)m * G4H + n] =
                make_float2(d[mf][nf][0] + bi0, d[mf][nf][1] + bi1);
            *(float2*)&out[(size_t)(m + 8) * G4H + n] =
                make_float2(d[mf][nf][2] + bi0, d[mf][nf][3] + bi1);
        }
    }
}

// ---------------------------------------------------------------------------
// Software grid barrier
// ---------------------------------------------------------------------------
__device__ __forceinline__ void grid_bar() {
    __syncthreads();
    if (threadIdx.x == 0) {
        __threadfence();
        const unsigned gen = *(volatile unsigned*)&g_bar_gen;
        if (atomicAdd(&g_bar_count, 1u) == NBLK - 1) {
            g_bar_count = 0;
            __threadfence();
            *(volatile unsigned*)&g_bar_gen = gen + 1;
        } else {
            while (*(volatile unsigned*)&g_bar_gen == gen) {}
        }
        __threadfence();
    }
    __syncthreads();
}

__device__ __forceinline__ void cell_update(int layer, int cidx, float v0, float v1,
                                            float v2, float v3) {
    const float ig = 1.0f / (1.0f + expf(-v0));
    const float fg = 1.0f / (1.0f + expf(-v1));
    const float gg = tanhf(v2);
    const float og = 1.0f / (1.0f + expf(-v3));
    const float c_new = fg * g_c[layer][cidx] + ig * gg;
    g_c[layer][cidx] = c_new;
    const float h = og * tanhf(c_new);
    g_h[layer][cidx] = h;
    const bf16 hi = __float2bfloat16_rn(h);
    g_hhi[layer][cidx] = hi;
    g_hlo[layer][cidx] = __float2bfloat16_rn(h - __bfloat162float(hi));
}

// ---------------------------------------------------------------------------
// Persistent recurrence: TMA-staged GEMMs, 2 grid barriers/tick.
//   gemm phase (unified, NW = 6): w0-3 = L1(t) K=256 -> gp1; w4-5 = L0(t+1) -> gp0
// mbarrier parity: window global index g -> bar g&1, phase (g>>1)&1.
// ---------------------------------------------------------------------------
__global__ __launch_bounds__(256, 2) void lstm_persistent_kernel(
    const __grid_constant__ CUtensorMap mA0h, const __grid_constant__ CUtensorMap mA0l,
    const __grid_constant__ CUtensorMap mA1h, const __grid_constant__ CUtensorMap mA1l,
    const __grid_constant__ CUtensorMap mB0h, const __grid_constant__ CUtensorMap mB0l,
    const __grid_constant__ CUtensorMap mBih, const __grid_constant__ CUtensorMap mBil,
    const __grid_constant__ CUtensorMap mBhh, const __grid_constant__ CUtensorMap mBhl,
    const float* __restrict__ b_ih1, const float* __restrict__ b_hh1)
{
    extern __shared__ __align__(1024) char sm[];
    const uint32_t smem_u = (uint32_t)__cvta_generic_to_shared(sm);
    const uint32_t mbar_u = smem_u + 2 * BUFB;
    const int tid = threadIdx.x;
    const int bid = blockIdx.x;
    const int nt = bid & 31, ks = bid >> 5;
    const int n0 = nt * 128;
    const int cidx = bid * 256 + tid;
    const int cm = cidx >> 10, cj = cidx & (HID - 1);

    // L1 operand selection: ks<4 -> h0 x W_ih1, ks>=4 -> h1 x W_hh1
    const int ks1 = (ks < 4) ? ks * 256 : (ks - 4) * 256;
    const CUtensorMap* A1h = (ks < 4) ? &mA0h : &mA1h;
    const CUtensorMap* A1l = (ks < 4) ? &mA0l : &mA1l;
    const CUtensorMap* B1h = (ks < 4) ? &mBih : &mBhh;
    const CUtensorMap* B1l = (ks < 4) ? &mBil : &mBhl;

    float* gp1_out = g_gp1 + (size_t)ks * BATCH * G4H;
    float* gp0_out = g_gp0 + (size_t)ks * BATCH * G4H;

    if (tid == 0) { mbar_init(mbar_u, 1); mbar_init(mbar_u + 8, 1); }
    __syncthreads();

    unsigned g = 0;   // global window counter (drives bar slot + parity)

    // prologue: L0 GEMM for t=0 (2 windows)
    {
        if (tid == 0)
#pragma unroll
            for (int w = 0; w < 2; w++)
                issue_win2d(smem_u + ((g + w) & 1) * BUFB, mbar_u + ((g + w) & 1) * 8,
                            &mA0h, &mA0l, ks * 128 + w * 64,
                            &mB0h, &mB0l, ks * 128 + w * 64, n0);
        float d[4][2][4];
        zero_acc(d);
#pragma unroll 1
        for (int w = 0; w < 2; w++) {
            const unsigned gl = g + w;
            mbar_wait(mbar_u + (gl & 1) * 8, (gl >> 1) & 1);
            mma_win64(smem_u + (gl & 1) * BUFB, d);
            __syncthreads();
        }
        g += 2;
        store_frags(gp0_out, G4H, n0, d);
    }
    grid_bar();

#pragma unroll 1
    for (int t = 0; t < S_LEN; ++t) {
        // ---- cell phase ----
        {
            float v[4];
#pragma unroll
            for (int gt = 0; gt < 4; gt++) {
                const int n = gt * HID + cj;
                float s = g_XW0[((size_t)t * BATCH + cm) * G4H + n];
#pragma unroll
                for (int ss = 0; ss < KSPLIT; ss++)
                    s += g_gp0[((size_t)ss * BATCH + cm) * G4H + n];
                v[gt] = s;
            }
            cell_update(0, cidx, v[0], v[1], v[2], v[3]);

            if (t > 0) {
#pragma unroll
                for (int gt = 0; gt < 4; gt++) {
                    const int n = gt * HID + cj;
                    float s = b_ih1[n] + b_hh1[n];
#pragma unroll
                    for (int ss = 0; ss < KSPLIT; ss++)
                        s += g_gp1[((size_t)ss * BATCH + cm) * G4H + n];
                    v[gt] = s;
                }
                cell_update(1, cidx, v[0], v[1], v[2], v[3]);
            }
        }
        grid_bar();

        // ---- unified gemm phase: 4 L1 windows (+2 L0 windows) ----
        {
            const int NW = (t + 1 < S_LEN) ? 6 : 4;
            if (tid == 0)
#pragma unroll
                for (int w = 0; w < 2; w++)   // L1 w0,w1
                    issue_win2d(smem_u + ((g + w) & 1) * BUFB, mbar_u + ((g + w) & 1) * 8,
                                A1h, A1l, ks1 + w * 64, B1h, B1l, ks1 + w * 64, n0);
            float d[4][2][4];
            zero_acc(d);
#pragma unroll 1
            for (int w = 0; w < NW; w++) {
                const unsigned gl = g + w;
                mbar_wait(mbar_u + (gl & 1) * 8, (gl >> 1) & 1);
                mma_win64(smem_u + (gl & 1) * BUFB, d);
                __syncthreads();
                const int w2 = w + 2;
                if (tid == 0 && w2 < NW) {
                    const unsigned g2 = g + w2;
                    const uint32_t buf = smem_u + (g2 & 1) * BUFB;
                    const uint32_t bar = mbar_u + (g2 & 1) * 8;
                    if (w2 < 4)
                        issue_win2d(buf, bar, A1h, A1l, ks1 + w2 * 64,
                                    B1h, B1l, ks1 + w2 * 64, n0);
                    else
                        issue_win2d(buf, bar, &mA0h, &mA0l, ks * 128 + (w2 - 4) * 64,
                                    &mB0h, &mB0l, ks * 128 + (w2 - 4) * 64, n0);
                }
                if (w == 3) {
                    store_frags(gp1_out, G4H, n0, d);
                    zero_acc(d);
                }
            }
            g += NW;
            if (NW == 6) store_frags(gp0_out, G4H, n0, d);
        }
        grid_bar();
    }

    // final cell1(S_LEN-1)
    {
        float v[4];
#pragma unroll
        for (int gt = 0; gt < 4; gt++) {
            const int n = gt * HID + cj;
            float s = b_ih1[n] + b_hh1[n];
#pragma unroll
            for (int ss = 0; ss < KSPLIT; ss++)
                s += g_gp1[((size_t)ss * BATCH + cm) * G4H + n];
            v[gt] = s;
        }
        cell_update(1, cidx, v[0], v[1], v[2], v[3]);
    }
}

// ---------------------------------------------------------------------------
// Final FC: out = h1 @ W_fc^T + b_fc
// ---------------------------------------------------------------------------
__global__ void fc_kernel(const float* __restrict__ Wfc,
                          const float* __restrict__ bfc,
                          float* __restrict__ out)
{
    const int gwarp = (blockIdx.x * blockDim.x + threadIdx.x) >> 5;
    const int lane  = threadIdx.x & 31;
    if (gwarp >= BATCH * OUTN) return;
    const int m = gwarp / OUTN;
    const int o = gwarp % OUTN;
    const float* hp = g_h[1] + (size_t)m * HID;
    const float* wp = Wfc + (size_t)o * HID;
    float s = 0.0f;
#pragma unroll 8
    for (int k = lane; k < HID; k += 32) s += hp[k] * wp[k];
#pragma unroll
    for (int off = 16; off; off >>= 1) s += __shfl_xor_sync(0xffffffffu, s, off);
    if (lane == 0) out[m * OUTN + o] = s + bfc[o];
}

// ---------------------------------------------------------------------------
// Host: tensormap construction (driver entry point, no -lcuda needed)
// ---------------------------------------------------------------------------
typedef CUresult (*TmapEncodeFn)(CUtensorMap*, CUtensorMapDataType, cuuint32_t, void*,
                                 const cuuint64_t*, const cuuint64_t*, const cuuint32_t*,
                                 const cuuint32_t*, CUtensorMapInterleave, CUtensorMapSwizzle,
                                 CUtensorMapL2promotion, CUtensorMapFloatOOBfill);

static TmapEncodeFn tmap_fn() {
    static TmapEncodeFn fn = nullptr;
    if (!fn) {
        void* p = nullptr;
        cudaDriverEntryPointQueryResult qr;
        cudaGetDriverEntryPoint("cuTensorMapEncodeTiled", &p, cudaEnableDefault, &qr);
        fn = (TmapEncodeFn)p;
    }
    return fn;
}

static void make2d(CUtensorMap* m, void* base, uint64_t d0, uint64_t d1,
                   uint64_t stride1B, uint32_t b0, uint32_t b1) {
    cuuint64_t dims[2] = {d0, d1};
    cuuint64_t strides[1] = {stride1B};
    cuuint32_t box[2] = {b0, b1};
    cuuint32_t es[2] = {1, 1};
    tmap_fn()(m, CU_TENSOR_MAP_DATA_TYPE_BFLOAT16, 2, base, dims, strides, box, es,
              CU_TENSOR_MAP_INTERLEAVE_NONE, CU_TENSOR_MAP_SWIZZLE_128B,
              CU_TENSOR_MAP_L2_PROMOTION_L2_128B, CU_TENSOR_MAP_FLOAT_OOB_FILL_NONE);
}
static void make3d(CUtensorMap* m, void* base, uint64_t d0, uint64_t d1, uint64_t d2,
                   uint64_t s1B, uint64_t s2B, uint32_t b0, uint32_t b1, uint32_t b2) {
    cuuint64_t dims[3] = {d0, d1, d2};
    cuuint64_t strides[2] = {s1B, s2B};
    cuuint32_t box[3] = {b0, b1, b2};
    cuuint32_t es[3] = {1, 1, 1};
    tmap_fn()(m, CU_TENSOR_MAP_DATA_TYPE_BFLOAT16, 3, base, dims, strides, box, es,
              CU_TENSOR_MAP_INTERLEAVE_NONE, CU_TENSOR_MAP_SWIZZLE_128B,
              CU_TENSOR_MAP_L2_PROMOTION_L2_128B, CU_TENSOR_MAP_FLOAT_OOB_FILL_NONE);
}

extern "C" void kernel_launch(void* const* d_in, const int* in_sizes, int n_in,
                              void* d_out, int out_size) {
    const float* x      = (const float*)d_in[0];
    const float* h0     = (const float*)d_in[1];
    const float* c0     = (const float*)d_in[2];
    const float* W_ih0  = (const float*)d_in[3];
    const float* W_hh0  = (const float*)d_in[4];
    const float* b_ih0  = (const float*)d_in[5];
    const float* b_hh0  = (const float*)d_in[6];
    const float* W_ih1  = (const float*)d_in[7];
    const float* W_hh1  = (const float*)d_in[8];
    const float* b_ih1  = (const float*)d_in[9];
    const float* b_hh1  = (const float*)d_in[10];
    const float* W_fc   = (const float*)d_in[11];
    const float* b_fc   = (const float*)d_in[12];
    float* out = (float*)d_out;

    cudaFuncSetAttribute(xw0_mma_kernel,
                         cudaFuncAttributeMaxDynamicSharedMemorySize, SMEM_BYTES);
    cudaFuncSetAttribute(lstm_persistent_kernel,
                         cudaFuncAttributeMaxDynamicSharedMemorySize, SMEM_BYTES);

    // symbol addresses for tensormaps
    void *whi, *wlo, *xhi, *xlo, *hhi, *hlo;
    cudaGetSymbolAddress(&whi, g_Whi);
    cudaGetSymbolAddress(&wlo, g_Wlo);
    cudaGetSymbolAddress(&xhi, g_xhi);
    cudaGetSymbolAddress(&xlo, g_xlo);
    cudaGetSymbolAddress(&hhi, g_hhi);
    cudaGetSymbolAddress(&hlo, g_hlo);

    // h maps: [64 rows x 1024 k], row stride 2048B, box 64k x 64rows
    CUtensorMap mA0h, mA0l, mA1h, mA1l;
    make2d(&mA0h, hhi, HID, BATCH, HID * 2, 64, 64);
    make2d(&mA0l, hlo, HID, BATCH, HID * 2, 64, 64);
    make2d(&mA1h, (char*)hhi + (size_t)BH * 2, HID, BATCH, HID * 2, 64, 64);
    make2d(&mA1l, (char*)hlo + (size_t)BH * 2, HID, BATCH, HID * 2, 64, 64);
    // weight maps: [4096 n x 1024 k], box 64k x 128n
    CUtensorMap mB0h, mB0l, mBih, mBil, mBhh, mBhl;
    make2d(&mB0h, (char*)whi + OFF_HH0 * 2, HID, G4H, HID * 2, 64, 128);
    make2d(&mB0l, (char*)wlo + OFF_HH0 * 2, HID, G4H, HID * 2, 64, 128);
    make2d(&mBih, (char*)whi + OFF_IH1 * 2, HID, G4H, HID * 2, 64, 128);
    make2d(&mBil, (char*)wlo + OFF_IH1 * 2, HID, G4H, HID * 2, 64, 128);
    make2d(&mBhh, (char*)whi + OFF_HH1 * 2, HID, G4H, HID * 2, 64, 128);
    make2d(&mBhl, (char*)wlo + OFF_HH1 * 2, HID, G4H, HID * 2, 64, 128);
    // x maps: 3D (d, t, m): dims {512, 512, 64}, strides {1024B, 524288B}, box {64,1,64}
    CUtensorMap mXh, mXl;
    make3d(&mXh, xhi, DIM, S_LEN, BATCH, DIM * 2, (uint64_t)S_LEN * DIM * 2, 64, 1, 64);
    make3d(&mXl, xlo, DIM, S_LEN, BATCH, DIM * 2, (uint64_t)S_LEN * DIM * 2, 64, 1, 64);
    // W_ih0 maps: [4096 n x 512 k], box 64k x 128n
    CUtensorMap mWh, mWl;
    make2d(&mWh, (char*)whi + OFF_IH0 * 2, DIM, G4H, DIM * 2, 64, 128);
    make2d(&mWl, (char*)wlo + OFF_IH0 * 2, DIM, G4H, DIM * 2, 64, 128);

    decomp_kernel<<<4096, 256>>>(W_hh0, W_ih1, W_hh1, W_ih0, x);
    init_state_kernel<<<512, 256>>>(h0, c0);
    xw0_mma_kernel<<<dim3(32, S_LEN), 256, SMEM_BYTES>>>(mXh, mXl, mWh, mWl, b_ih0, b_hh0);
    lstm_persistent_kernel<<<NBLK, 256, SMEM_BYTES>>>(
        mA0h, mA0l, mA1h, mA1l, mB0h, mB0l, mBih, mBil, mBhh, mBhl, b_ih1, b_hh1);
    fc_kernel<<<(BATCH * OUTN + 7) / 8, 256>>>(W_fc, b_fc, out);
}